// round 9
// baseline (speedup 1.0000x reference)
#include <cuda_runtime.h>
#include <cuda_fp16.h>
#include <cstdint>
#include <cstddef>

#define BB 128
#define TT 1000
#define II 64
#define HH 512
#define ALPHA 0.2f

#define CLUSTER 4
#define H_TILE 128      // h rows per CTA
#define NTHR 256        // 8 warps: warp = (K-half = wid>>2, M-pair = wid&3)
#define NWARP 8
#define KQ 36           // 576/16 k-steps (32 r + 4 x)
#define KH 18           // kq per warp
#define RCNT 2304       // u32 per buffer: 36*8*4*2

// rbuf u32 layout: idx(kq, n, m, j) = ((kq*8 + n)*4 + m)*2 + j
// u32(kq,n,m,j) = halves (k = 16kq + 8j + 2m, +1), column b = n.
// MMA B-frag read: lane-linear conflict-free LDS.64 per kq.
__device__ __forceinline__ int ridx(int kq, int n, int m, int j) {
    return ((kq * 8 + n) * 4 + m) * 2 + j;
}

static __device__ __forceinline__ uint32_t s2u(const void* p) {
    return (uint32_t)__cvta_generic_to_shared(p);
}
static __device__ __forceinline__ uint32_t h2_as_u32(half2 h) {
    uint32_t u; __builtin_memcpy(&u, &h, 4); return u;
}
static __device__ __forceinline__ void dsmem_st64(uint32_t addr, uint32_t rank, unsigned long long v) {
    uint32_t r;
    asm volatile("mapa.shared::cluster.u32 %0, %1, %2;" : "=r"(r) : "r"(addr), "r"(rank));
    asm volatile("st.shared::cluster.u64 [%0], %1;" :: "r"(r), "l"(v) : "memory");
}
static __device__ __forceinline__ void mbar_arrive_remote(uint32_t addr, uint32_t rank) {
    uint32_t r;
    asm volatile("mapa.shared::cluster.u32 %0, %1, %2;" : "=r"(r) : "r"(addr), "r"(rank));
    asm volatile("mbarrier.arrive.release.cluster.shared::cluster.b64 _, [%0];" :: "r"(r) : "memory");
}
static __device__ __forceinline__ void mbar_wait_acq(uint32_t addr, uint32_t parity) {
    asm volatile(
        "{.reg .pred P;\nWL%=:\n\t"
        "mbarrier.try_wait.parity.acquire.cluster.shared::cta.b64 P, [%0], %1;\n\t"
        "@!P bra WL%=;\n}"
        :: "r"(addr), "r"(parity) : "memory");
}
static __device__ __forceinline__ void mma_f16(float c[4], const uint32_t a[4], uint32_t b0, uint32_t b1) {
    asm volatile(
        "mma.sync.aligned.m16n8k16.row.col.f32.f16.f16.f32 "
        "{%0,%1,%2,%3}, {%4,%5,%6,%7}, {%8,%9}, {%0,%1,%2,%3};"
        : "+f"(c[0]), "+f"(c[1]), "+f"(c[2]), "+f"(c[3])
        : "r"(a[0]), "r"(a[1]), "r"(a[2]), "r"(a[3]), "r"(b0), "r"(b1));
}
static __device__ __forceinline__ float tanh_fast(float x) {
    float y; asm("tanh.approx.f32 %0, %1;" : "=f"(y) : "f"(x)); return y;
}

// grid = 64 CTAs in 16 clusters of 4. Cluster g: b rows [g*8, g*8+8).
// CTA rank r: h rows [r*128, +128). Per step per CTA:
// drive[128h, 8b] = W_cat[128h, 576k] . rcat[8b, 576k], fp16 HMMA fp32 acc.
// Warp = (K-half, M-tile pair): each warp loads only its 18 B-frags (halves
// smem crossbar traffic); K-halves summed via cross-warp staging.
// Slot order (K dim): 0..7 own-rank r block, 8..11 x, 12..35 peers in ring
// order. Half 0 = slots 0..17 (local slots first -> pre-wait MMA), half 1 = 18..35.
__global__ void __launch_bounds__(NTHR, 1) __cluster_dims__(CLUSTER, 1, 1)
rnn_kernel(const float* __restrict__ x, const float* __restrict__ W_in,
           const float* __restrict__ b_in, const float* __restrict__ W_hh,
           const float* __restrict__ b_hh, float* __restrict__ out_r)
{
    const int tid  = threadIdx.x;
    const int wid  = tid >> 5;
    const int lane = tid & 31;
    const int rank = blockIdx.x & (CLUSTER - 1);
    const int bg   = blockIdx.x >> 2;
    const int hbase = rank * H_TILE;
    const int b0g   = bg * 8;
    const int half  = wid >> 2;          // K half
    const int mq    = wid & 3;           // M-tile pair: mtiles 2mq, 2mq+1

    __shared__ __align__(16) uint32_t rbuf[2][RCNT];
    __shared__ __align__(16) float stg[2][H_TILE][12];
    __shared__ __align__(8) unsigned long long mbar;

    if (tid == 0)
        asm volatile("mbarrier.init.shared.b64 [%0], %1;"
                     :: "r"(s2u(&mbar)), "r"(CLUSTER) : "memory");

    // zero buf0 (r(0) = 0; x region overwritten below)
    for (int i = tid; i < RCNT; i += NTHR) rbuf[0][i] = 0u;

    const int r1 = (rank + 1) & 3, r2 = (rank + 2) & 3, r3 = (rank + 3) & 3;

    // ---- W fragments (A operand), slot order, packed fp16, once ----
    const int kA = 2 * (lane & 3);
    uint32_t a[2][KH][4];
#pragma unroll
    for (int m = 0; m < 2; m++) {
        const int hA = hbase + (2 * mq + m) * 16 + (lane >> 2);
#pragma unroll
        for (int s = 0; s < KH; s++) {
            int sg = half * KH + s;
            int kq_phys;
            if (sg < 8)       kq_phys = rank * 8 + sg;
            else if (sg < 12) kq_phys = 32 + (sg - 8);
            else {
                int c = (sg - 12) >> 3, i = (sg - 12) & 7;
                kq_phys = (((rank + 1 + c) & 3) << 3) + i;
            }
#pragma unroll
            for (int j = 0; j < 4; j++) {
                int h = hA + ((j & 1) ? 8 : 0);
                int k = kq_phys * 16 + kA + ((j & 2) ? 8 : 0);
                float2 w;
                if (k < HH) w = *(const float2*)&W_hh[h * HH + k];
                else        w = *(const float2*)&W_in[h * II + (k - HH)];
                a[m][s][j] = h2_as_u32(__floats2half2_rn(w.x, w.y));
            }
        }
    }

    // ---- epilogue / writer mapping ----
    const int wn = lane >> 2;            // local b 0..7
    const int wm = lane & 3;             // fragment m 0..3
    const int ebg = b0g + wn;
    const int kq_g = rank * 8 + wid;     // global kq of owned r slice
    const int hl0 = wid * 16 + 2 * wm;   // owned h: hl0, +1, +8, +9
    float bias_r[4];
#pragma unroll
    for (int i = 0; i < 4; i++) {
        int hl = hl0 + ((i >> 1) ? 8 : 0) + (i & 1);
        bias_r[i] = b_hh[hbase + hl] + b_in[hbase + hl];
    }
    float r_old[4] = {0.f, 0.f, 0.f, 0.f};
    const int sidx = ridx(kq_g, wn, wm, 0);

    // ---- x staging mapping: one u32 per thread ----
    const int xj  = tid & 1;
    const int xm  = (tid >> 1) & 3;
    const int xkq = 32 + ((tid >> 3) & 3);
    const int xn  = tid >> 5;
    const int xi0 = (xkq - 32) * 16 + xj * 8 + 2 * xm;
    const float* xrow = &x[(size_t)(b0g + xn) * TT * II + xi0];
    const int xidx = ridx(xkq, xn, xm, xj);

    // stage x(0)
    {
        float2 xv = *(const float2*)&xrow[0];
        rbuf[0][xidx] = h2_as_u32(__floats2half2_rn(xv.x, xv.y));
    }
    __syncthreads();
    asm volatile("barrier.cluster.arrive.aligned;" ::: "memory");
    asm volatile("barrier.cluster.wait.aligned;"   ::: "memory");

    const uint32_t mbar_a = s2u(&mbar);
    // prologue arrive round: completes phase 0 so wait(parity 0) at t=0 passes
    if (tid < CLUSTER) mbar_arrive_remote(mbar_a, (uint32_t)tid);

#pragma unroll 1
    for (int t = 0; t < TT; t++) {
        const int p = t & 1;
        int tn = (t + 1 < TT) ? t + 1 : TT - 1;
        float2 xv = *(const float2*)&xrow[(size_t)tn * II];

        const uint32_t* rbp = &rbuf[p][lane * 2];

        float c[2][2][4];
#pragma unroll
        for (int m = 0; m < 2; m++)
#pragma unroll
            for (int q = 0; q < 2; q++)
#pragma unroll
                for (int r = 0; r < 4; r++) c[m][q][r] = 0.f;

        if (half == 0) {
            const uint32_t* pown = rbp + rank * 512;
            const uint32_t* px   = rbp + 2048;
            const uint32_t* pr1  = rbp + r1 * 512;
            // phase 1: local slots 0..11 (own r + x)
#pragma unroll
            for (int i = 0; i < 8; i++) {
                uint2 bv = *(const uint2*)&pown[i * 64];
                mma_f16(c[0][i & 1], a[0][i], bv.x, bv.y);
                mma_f16(c[1][i & 1], a[1][i], bv.x, bv.y);
            }
#pragma unroll
            for (int i = 0; i < 4; i++) {
                uint2 bv = *(const uint2*)&px[i * 64];
                mma_f16(c[0][i & 1], a[0][8 + i], bv.x, bv.y);
                mma_f16(c[1][i & 1], a[1][8 + i], bv.x, bv.y);
            }
            mbar_wait_acq(mbar_a, (uint32_t)p);
            // phase 2: slots 12..17 = r1 blocks 0..5
#pragma unroll
            for (int i = 0; i < 6; i++) {
                uint2 bv = *(const uint2*)&pr1[i * 64];
                mma_f16(c[0][i & 1], a[0][12 + i], bv.x, bv.y);
                mma_f16(c[1][i & 1], a[1][12 + i], bv.x, bv.y);
            }
        } else {
            const uint32_t* pr1 = rbp + r1 * 512;
            const uint32_t* pr2 = rbp + r2 * 512;
            const uint32_t* pr3 = rbp + r3 * 512;
            mbar_wait_acq(mbar_a, (uint32_t)p);
            // slots 18..35 = r1 blocks 6,7; r2 0..7; r3 0..7
#pragma unroll
            for (int i = 0; i < 2; i++) {
                uint2 bv = *(const uint2*)&pr1[(6 + i) * 64];
                mma_f16(c[0][i & 1], a[0][i], bv.x, bv.y);
                mma_f16(c[1][i & 1], a[1][i], bv.x, bv.y);
            }
#pragma unroll
            for (int i = 0; i < 8; i++) {
                uint2 bv = *(const uint2*)&pr2[i * 64];
                mma_f16(c[0][i & 1], a[0][2 + i], bv.x, bv.y);
                mma_f16(c[1][i & 1], a[1][2 + i], bv.x, bv.y);
            }
#pragma unroll
            for (int i = 0; i < 8; i++) {
                uint2 bv = *(const uint2*)&pr3[i * 64];
                mma_f16(c[0][i & 1], a[0][10 + i], bv.x, bv.y);
                mma_f16(c[1][i & 1], a[1][10 + i], bv.x, bv.y);
            }
        }

        // ---- stage partials: stg[half][h][b] ----
        {
            int rr = lane >> 2, cc = 2 * (lane & 3);
#pragma unroll
            for (int m = 0; m < 2; m++) {
                int hb = (2 * mq + m) * 16;
                float2 lo = make_float2(c[m][0][0] + c[m][1][0], c[m][0][1] + c[m][1][1]);
                float2 hi = make_float2(c[m][0][2] + c[m][1][2], c[m][0][3] + c[m][1][3]);
                *(float2*)&stg[half][hb + rr][cc]     = lo;
                *(float2*)&stg[half][hb + rr + 8][cc] = hi;
            }
        }
        __syncthreads();

        // ---- epilogue: sum halves + tanh + leaky update ----
        float rn[4];
#pragma unroll
        for (int i = 0; i < 4; i++) {
            int hl = hl0 + ((i >> 1) ? 8 : 0) + (i & 1);
            float s = stg[0][hl][wn] + stg[1][hl][wn] + bias_r[i];
            float d = tanh_fast(s);
            rn[i] = (1.0f - ALPHA) * r_old[i] + ALPHA * d;
            r_old[i] = rn[i];
        }

        // ---- broadcast owned fragment pair into next buffer ----
        unsigned long long pv =
            (unsigned long long)h2_as_u32(__floats2half2_rn(rn[0], rn[1]))
            | ((unsigned long long)h2_as_u32(__floats2half2_rn(rn[2], rn[3])) << 32);
        uint32_t* dstb = rbuf[p ^ 1];
        *(unsigned long long*)&dstb[sidx] = pv;            // self
        uint32_t daddr = s2u(&dstb[sidx]);
#pragma unroll
        for (int cc = 1; cc < CLUSTER; cc++)
            dsmem_st64(daddr, (uint32_t)((rank + cc) & (CLUSTER - 1)), pv);
        // stage x(t+1)
        dstb[xidx] = h2_as_u32(__floats2half2_rn(xv.x, xv.y));

        __syncthreads();
        if (tid < CLUSTER) mbar_arrive_remote(mbar_a, (uint32_t)tid);

        // out_r store — overlaps next step's pre-wait work
        {
            size_t ob = ((size_t)t * BB + ebg) * HH + hbase + hl0;
            *(float2*)&out_r[ob]     = make_float2(rn[0], rn[1]);
            *(float2*)&out_r[ob + 8] = make_float2(rn[2], rn[3]);
        }
    }

    // terminal cluster sync: no CTA may exit while peers' DSMEM stores /
    // mbarrier arrives targeting this CTA's SMEM can still be in flight.
    asm volatile("barrier.cluster.arrive.aligned;" ::: "memory");
    asm volatile("barrier.cluster.wait.aligned;"   ::: "memory");
}

// decision[t,b] = dot(output[t,b,:], W_out) + b_out   (1 warp per row)
__global__ void __launch_bounds__(256)
decision_kernel(const float* __restrict__ out_r, const float* __restrict__ W_out,
                const float* __restrict__ b_out, float* __restrict__ dec)
{
    int wg = blockIdx.x * 8 + (threadIdx.x >> 5);
    int lane = threadIdx.x & 31;
    if (wg >= TT * BB) return;
    const float* row = out_r + (size_t)wg * HH;
    float s = 0.0f;
#pragma unroll
    for (int c = 0; c < 4; c++) {
        int h = c * 128 + lane * 4;
        float4 v = *(const float4*)&row[h];
        float4 w = *(const float4*)&W_out[h];
        s += v.x * w.x + v.y * w.y + v.z * w.z + v.w * w.w;
    }
#pragma unroll
    for (int o = 16; o; o >>= 1) s += __shfl_down_sync(0xffffffffu, s, o);
    if (lane == 0) dec[wg] = s + b_out[0];
}

extern "C" void kernel_launch(void* const* d_in, const int* in_sizes, int n_in,
                              void* d_out, int out_size) {
    const float* x     = (const float*)d_in[0];
    const float* W_in  = (const float*)d_in[1];
    const float* b_in  = (const float*)d_in[2];
    const float* W_hh  = (const float*)d_in[3];
    const float* b_hh  = (const float*)d_in[4];
    const float* W_out = (const float*)d_in[5];
    const float* b_out = (const float*)d_in[6];

    float* dec   = (float*)d_out;                    // [T*B]
    float* out_r = (float*)d_out + (size_t)TT * BB;  // [T*B*H]

    rnn_kernel<<<BB / 2, NTHR>>>(x, W_in, b_in, W_hh, b_hh, out_r);
    decision_kernel<<<(TT * BB) / 8, 256>>>(out_r, W_out, b_out, dec);
}